// round 3
// baseline (speedup 1.0000x reference)
#include <cuda_runtime.h>
#include <math.h>

#define EPSF 1e-8f
#define BIGF 1e10f
#define MAXB 8
#define MAXF 4096

#define TILE_W 16
#define TILE_H 16
#define NTHREADS 128
#define TCHUNK 256

// Scratch: compacted per-batch triangle setup data + bboxes + counters.
__device__ float4 g_tri[MAXB * MAXF * 4];   // d0,d1,d2,d3 per triangle
__device__ float4 g_bbox[MAXB * MAXF];      // xmin,xmax,ymin,ymax
__device__ int    g_cnt[MAXB];

__global__ void dr_init_kernel() {
    if (threadIdx.x < MAXB) g_cnt[threadIdx.x] = 0;
}

// One thread per (batch, face): project 3 vertices, build edge-function setup,
// cull invalid triangles, append to compacted list.
__global__ void dr_setup_kernel(const float* __restrict__ mesh,
                                const float* __restrict__ Rm,
                                const float* __restrict__ tv,
                                const float* __restrict__ focal,
                                const float* __restrict__ princpt,
                                const int*   __restrict__ face,
                                int B, int V, int F) {
    int idx = blockIdx.x * blockDim.x + threadIdx.x;
    if (idx >= B * F) return;
    int b = idx / F;
    int f = idx - b * F;

    const float* Rb = Rm + b * 9;
    float t0 = tv[b * 3 + 0], t1 = tv[b * 3 + 1], t2 = tv[b * 3 + 2];
    float fx = focal[b * 2 + 0], fy = focal[b * 2 + 1];
    float cx = princpt[b * 2 + 0], cy = princpt[b * 2 + 1];

    float X[3], Y[3], Z[3];
#pragma unroll
    for (int k = 0; k < 3; k++) {
        int v = face[f * 3 + k];
        const float* m = mesh + ((long)b * V + v) * 3;
        float m0 = m[0], m1 = m[1], m2 = m[2];
        // einsum sum order j=0..2, then + t  (exact rn ops, no contraction)
        float c0 = __fadd_rn(__fadd_rn(__fmul_rn(Rb[0], m0), __fmul_rn(Rb[1], m1)), __fmul_rn(Rb[2], m2));
        float c1 = __fadd_rn(__fadd_rn(__fmul_rn(Rb[3], m0), __fmul_rn(Rb[4], m1)), __fmul_rn(Rb[5], m2));
        float c2 = __fadd_rn(__fadd_rn(__fmul_rn(Rb[6], m0), __fmul_rn(Rb[7], m1)), __fmul_rn(Rb[8], m2));
        c0 = __fadd_rn(c0, t0);
        c1 = __fadd_rn(c1, t1);
        c2 = __fadd_rn(c2, t2);
        float zs = (fabsf(c2) > EPSF) ? c2 : EPSF;
        X[k] = __fadd_rn(__fdiv_rn(__fmul_rn(fx, c0), zs), cx);
        Y[k] = __fadd_rn(__fdiv_rn(__fmul_rn(fy, c1), zs), cy);
        Z[k] = c2;
    }

    // area = (x1-x0)*(y2-y0) - (y1-y0)*(x2-x0)   (reference rounding)
    float area = __fsub_rn(__fmul_rn(__fsub_rn(X[1], X[0]), __fsub_rn(Y[2], Y[0])),
                           __fmul_rn(__fsub_rn(Y[1], Y[0]), __fsub_rn(X[2], X[0])));
    if (!(fabsf(area) > EPSF)) return;                       // invalid area -> never contributes
    if (!(fminf(Z[0], fminf(Z[1], Z[2])) > EPSF)) return;    // not front -> never contributes

    float iz0 = __fdiv_rn(Z[0], area);
    float iz1 = __fdiv_rn(Z[1], area);
    float iz2 = __fdiv_rn(Z[2], area);

    int p = atomicAdd(&g_cnt[b], 1);
    float4* o = &g_tri[((long)b * MAXF + p) * 4];
    // w0 = (x2-x1)*(py-y1) - (y2-y1)*(px-x1)  -> (e0x, e0y, x1, y1)
    o[0] = make_float4(__fsub_rn(X[2], X[1]), __fsub_rn(Y[2], Y[1]), X[1], Y[1]);
    // w1 = (x0-x2)*(py-y2) - (y0-y2)*(px-x2)  -> (e1x, e1y, x2, y2)
    o[1] = make_float4(__fsub_rn(X[0], X[2]), __fsub_rn(Y[0], Y[2]), X[2], Y[2]);
    // w2 = (x1-x0)*(py-y0) - (y1-y0)*(px-x0)  -> (e2x, e2y, x0, y0)
    o[2] = make_float4(__fsub_rn(X[1], X[0]), __fsub_rn(Y[1], Y[0]), X[0], Y[0]);
    o[3] = make_float4(iz0, iz1, iz2, 0.f);

    float xmin = fminf(X[0], fminf(X[1], X[2]));
    float xmax = fmaxf(X[0], fmaxf(X[1], X[2]));
    float ymin = fminf(Y[0], fminf(Y[1], Y[2]));
    float ymax = fmaxf(Y[0], fmaxf(Y[1], Y[2]));
    g_bbox[(long)b * MAXF + p] = make_float4(xmin, xmax, ymin, ymax);
}

// Conservative interval of affine w over a pixel-center rectangle:
// wc at rect center, radius = |ex|*hy + |ey|*hx, padded for fp slop.
__device__ __forceinline__ void edge_range(float ex, float ey, float ax, float ay,
                                           float cx, float cy, float hx, float hy,
                                           float& wmin, float& wmax) {
    float wc = ex * (cy - ay) - ey * (cx - ax);
    float r  = fabsf(ex) * hy + fabsf(ey) * hx;
    float pad = 1e-5f * (fabsf(wc) + r) + 1e-5f;
    wmin = wc - r - pad;
    wmax = wc + r + pad;
}

__device__ __forceinline__ bool rect_may_hit(float4 e0, float4 e1, float4 e2,
                                             float cx, float cy, float hx, float hy) {
    float mn0, mx0, mn1, mx1, mn2, mx2;
    edge_range(e0.x, e0.y, e0.z, e0.w, cx, cy, hx, hy, mn0, mx0);
    edge_range(e1.x, e1.y, e1.z, e1.w, cx, cy, hx, hy, mn1, mx1);
    edge_range(e2.x, e2.y, e2.z, e2.w, cx, cy, hx, hy, mn2, mx2);
    bool pos_ok = (mx0 >= 0.f) && (mx1 >= 0.f) && (mx2 >= 0.f);
    bool neg_ok = (mn0 <= 0.f) && (mn1 <= 0.f) && (mn2 <= 0.f);
    return pos_ok || neg_ok;
}

// 16x16 pixel tile per block, 128 threads. Each warp owns an 8x8 quadrant
// (4 col-threads * 2px * 8 rows). Two-level cull: block-level (bbox + tile
// edge intervals) into SMEM, then per-warp quadrant interval cull with
// ballot compaction into a per-warp index list.
__global__ __launch_bounds__(NTHREADS)
void dr_raster_kernel(float* __restrict__ out, int W, int H) {
    __shared__ float4 sdata[TCHUNK * 4];
    __shared__ short  swlist[4][TCHUNK];
    __shared__ int scount;

    int b = blockIdx.z;
    int tile_x0 = blockIdx.x * TILE_W;
    int tile_y0 = blockIdx.y * TILE_H;
    int tid = threadIdx.x;
    int warp = tid >> 5;
    int lane = tid & 31;
    int qx = warp & 1;       // quadrant col (0..1)
    int qy = warp >> 1;      // quadrant row (0..1)
    int tx = lane & 3;       // 4 column-threads * 2 px = 8 px
    int ty = lane >> 2;      // 8 rows

    int row  = tile_y0 + qy * 8 + ty;
    int col0 = tile_x0 + qx * 8 + tx * 2;
    float py  = (float)row + 0.5f;
    float px0 = (float)col0 + 0.5f;

    float zmin0 = BIGF, zmin1 = BIGF;

    int cnt = g_cnt[b];
    // tile rect (pixel centers)
    float tcx = (float)tile_x0 + 0.5f * (float)TILE_W;   // center of [x0+0.5, x0+15.5]
    float tcy = (float)tile_y0 + 0.5f * (float)TILE_H;
    float thx = 0.5f * (float)(TILE_W - 1);
    float thy = 0.5f * (float)(TILE_H - 1);
    float tminx = (float)tile_x0 + 0.5f;
    float tmaxx = (float)(tile_x0 + TILE_W - 1) + 0.5f;
    float tminy = (float)tile_y0 + 0.5f;
    float tmaxy = (float)(tile_y0 + TILE_H - 1) + 0.5f;
    // quadrant rect (pixel centers): 8x8 starting at tile + q*8
    float qcx = (float)(tile_x0 + qx * 8) + 4.0f;        // center of [+0.5, +7.5]
    float qcy = (float)(tile_y0 + qy * 8) + 4.0f;
    float qhx = 3.5f, qhy = 3.5f;

    const float4* tri = &g_tri[(long)b * MAXF * 4];
    const float4* bbx = &g_bbox[(long)b * MAXF];

    for (int base = 0; base < cnt; base += TCHUNK) {
        if (tid == 0) scount = 0;
        __syncthreads();
        int n = min(TCHUNK, cnt - base);
        // Level 1: block cull (bbox pre-filter + tile edge intervals)
        for (int i = tid; i < n; i += NTHREADS) {
            float4 bb = bbx[base + i];
            if (bb.y >= tminx && bb.x <= tmaxx && bb.w >= tminy && bb.z <= tmaxy) {
                const float4* s = &tri[(long)(base + i) * 4];
                float4 e0 = s[0], e1 = s[1], e2 = s[2];
                if (rect_may_hit(e0, e1, e2, tcx, tcy, thx, thy)) {
                    int p = atomicAdd(&scount, 1);
                    sdata[p * 4 + 0] = e0;
                    sdata[p * 4 + 1] = e1;
                    sdata[p * 4 + 2] = e2;
                    sdata[p * 4 + 3] = s[3];
                }
            }
        }
        __syncthreads();
        int m = scount;

        // Level 2: per-warp quadrant cull with ballot compaction
        int wm = 0;
        for (int i = lane; i < ((m + 31) & ~31); i += 32) {
            bool pass = false;
            if (i < m) {
                float4 e0 = sdata[i * 4 + 0];
                float4 e1 = sdata[i * 4 + 1];
                float4 e2 = sdata[i * 4 + 2];
                pass = rect_may_hit(e0, e1, e2, qcx, qcy, qhx, qhy);
            }
            unsigned bal = __ballot_sync(0xffffffffu, pass);
            if (pass) {
                int pos = wm + __popc(bal & ((1u << lane) - 1u));
                swlist[warp][pos] = (short)i;
            }
            wm += __popc(bal);
        }

        // Inner loop: only this warp's survivors (warp-uniform trip count)
        for (int jj = 0; jj < wm; jj++) {
            int j = swlist[warp][jj];
            float4 d0 = sdata[j * 4 + 0];
            float4 d1 = sdata[j * 4 + 1];
            float4 d2 = sdata[j * 4 + 2];
            float4 d3 = sdata[j * 4 + 3];
            // row-shared terms (reference rounding preserved)
            float a0 = __fmul_rn(d0.x, __fsub_rn(py, d0.w));
            float a1 = __fmul_rn(d1.x, __fsub_rn(py, d1.w));
            float a2 = __fmul_rn(d2.x, __fsub_rn(py, d2.w));
#pragma unroll
            for (int k = 0; k < 2; k++) {
                float px = px0 + (float)k;
                float w0 = __fsub_rn(a0, __fmul_rn(d0.y, __fsub_rn(px, d0.z)));
                float w1 = __fsub_rn(a1, __fmul_rn(d1.y, __fsub_rn(px, d1.z)));
                float w2 = __fsub_rn(a2, __fmul_rn(d2.y, __fsub_rn(px, d2.z)));
                bool inside = (w0 >= 0.f && w1 >= 0.f && w2 >= 0.f) ||
                              (w0 <= 0.f && w1 <= 0.f && w2 <= 0.f);
                float zi = __fmaf_rn(w0, d3.x, __fmaf_rn(w1, d3.y, __fmul_rn(w2, d3.z)));
                if (inside && zi > EPSF) {
                    if (k == 0) zmin0 = fminf(zmin0, zi);
                    else        zmin1 = fminf(zmin1, zi);
                }
            }
        }
        __syncthreads();
    }

    if (row < H) {
        float2 r;
        r.x = (zmin0 < 0.5f * BIGF) ? zmin0 : -1.f;
        r.y = (zmin1 < 0.5f * BIGF) ? zmin1 : -1.f;
        long off = ((long)b * H + row) * W + col0;
        if (col0 + 1 < W) {
            *(float2*)&out[off] = r;
        } else if (col0 < W) {
            out[off] = r.x;
        }
    }
}

extern "C" void kernel_launch(void* const* d_in, const int* in_sizes, int n_in,
                              void* d_out, int out_size) {
    const float* mesh    = (const float*)d_in[0];
    const float* Rm      = (const float*)d_in[1];
    const float* tv      = (const float*)d_in[2];
    const float* focal   = (const float*)d_in[3];
    const float* princpt = (const float*)d_in[4];
    const int*   face    = (const int*)  d_in[5];
    float* out = (float*)d_out;

    int B = in_sizes[1] / 9;            // R is (B,3,3)
    int V = in_sizes[0] / (3 * B);      // mesh is (B,V,3)
    int F = in_sizes[5] / 3;            // face is (F,3)
    int HW = out_size / B;              // out is (B,1,H,W)
    int W = (int)(sqrt((double)HW) + 0.5);
    int H = HW / W;

    dr_init_kernel<<<1, 32>>>();
    int nset = B * F;
    dr_setup_kernel<<<(nset + 255) / 256, 256>>>(mesh, Rm, tv, focal, princpt, face, B, V, F);
    dim3 grid((W + TILE_W - 1) / TILE_W, (H + TILE_H - 1) / TILE_H, B);
    dr_raster_kernel<<<grid, NTHREADS>>>(out, W, H);
}

// round 4
// speedup vs baseline: 1.1577x; 1.1577x over previous
#include <cuda_runtime.h>
#include <math.h>

#define EPSF 1e-8f
#define BIGF 1e10f
#define MAXB 8
#define MAXF 4096
#define MAXPIX (4 * 256 * 256)

#define TILE_W 16
#define TILE_H 16
#define NTHREADS 128
#define TCHUNK 256
#define SLICES 4

// Scratch (device globals; no dynamic allocation allowed)
__device__ float4       g_tri[MAXB * MAXF * 4];   // d0,d1,d2,d3 per triangle
__device__ float4       g_bbox[MAXB * MAXF];      // xmin,xmax,ymin,ymax
__device__ int          g_cnt[MAXB];
__device__ unsigned int g_zbuf[MAXPIX];           // uint-encoded positive float z

__global__ void dr_init_kernel(int npix) {
    int i = blockIdx.x * blockDim.x + threadIdx.x;
    if (i < MAXB) g_cnt[i] = 0;
    unsigned int big = __float_as_uint(BIGF);
    for (; i < npix; i += gridDim.x * blockDim.x) g_zbuf[i] = big;
}

// One thread per (batch, face): project 3 vertices, build edge-function setup,
// cull invalid triangles, append to compacted list.
__global__ void dr_setup_kernel(const float* __restrict__ mesh,
                                const float* __restrict__ Rm,
                                const float* __restrict__ tv,
                                const float* __restrict__ focal,
                                const float* __restrict__ princpt,
                                const int*   __restrict__ face,
                                int B, int V, int F) {
    int idx = blockIdx.x * blockDim.x + threadIdx.x;
    if (idx >= B * F) return;
    int b = idx / F;
    int f = idx - b * F;

    const float* Rb = Rm + b * 9;
    float t0 = tv[b * 3 + 0], t1 = tv[b * 3 + 1], t2 = tv[b * 3 + 2];
    float fx = focal[b * 2 + 0], fy = focal[b * 2 + 1];
    float cx = princpt[b * 2 + 0], cy = princpt[b * 2 + 1];

    float X[3], Y[3], Z[3];
#pragma unroll
    for (int k = 0; k < 3; k++) {
        int v = face[f * 3 + k];
        const float* m = mesh + ((long)b * V + v) * 3;
        float m0 = m[0], m1 = m[1], m2 = m[2];
        // einsum sum order j=0..2, then + t  (exact rn ops, no contraction)
        float c0 = __fadd_rn(__fadd_rn(__fmul_rn(Rb[0], m0), __fmul_rn(Rb[1], m1)), __fmul_rn(Rb[2], m2));
        float c1 = __fadd_rn(__fadd_rn(__fmul_rn(Rb[3], m0), __fmul_rn(Rb[4], m1)), __fmul_rn(Rb[5], m2));
        float c2 = __fadd_rn(__fadd_rn(__fmul_rn(Rb[6], m0), __fmul_rn(Rb[7], m1)), __fmul_rn(Rb[8], m2));
        c0 = __fadd_rn(c0, t0);
        c1 = __fadd_rn(c1, t1);
        c2 = __fadd_rn(c2, t2);
        float zs = (fabsf(c2) > EPSF) ? c2 : EPSF;
        X[k] = __fadd_rn(__fdiv_rn(__fmul_rn(fx, c0), zs), cx);
        Y[k] = __fadd_rn(__fdiv_rn(__fmul_rn(fy, c1), zs), cy);
        Z[k] = c2;
    }

    // area = (x1-x0)*(y2-y0) - (y1-y0)*(x2-x0)   (reference rounding)
    float area = __fsub_rn(__fmul_rn(__fsub_rn(X[1], X[0]), __fsub_rn(Y[2], Y[0])),
                           __fmul_rn(__fsub_rn(Y[1], Y[0]), __fsub_rn(X[2], X[0])));
    if (!(fabsf(area) > EPSF)) return;                       // invalid area -> never contributes
    if (!(fminf(Z[0], fminf(Z[1], Z[2])) > EPSF)) return;    // not front -> never contributes

    float iz0 = __fdiv_rn(Z[0], area);
    float iz1 = __fdiv_rn(Z[1], area);
    float iz2 = __fdiv_rn(Z[2], area);

    int p = atomicAdd(&g_cnt[b], 1);
    float4* o = &g_tri[((long)b * MAXF + p) * 4];
    // w0 = (x2-x1)*(py-y1) - (y2-y1)*(px-x1)  -> (e0x, e0y, x1, y1)
    o[0] = make_float4(__fsub_rn(X[2], X[1]), __fsub_rn(Y[2], Y[1]), X[1], Y[1]);
    // w1 = (x0-x2)*(py-y2) - (y0-y2)*(px-x2)  -> (e1x, e1y, x2, y2)
    o[1] = make_float4(__fsub_rn(X[0], X[2]), __fsub_rn(Y[0], Y[2]), X[2], Y[2]);
    // w2 = (x1-x0)*(py-y0) - (y1-y0)*(px-x0)  -> (e2x, e2y, x0, y0)
    o[2] = make_float4(__fsub_rn(X[1], X[0]), __fsub_rn(Y[1], Y[0]), X[0], Y[0]);
    o[3] = make_float4(iz0, iz1, iz2, 0.f);

    float xmin = fminf(X[0], fminf(X[1], X[2]));
    float xmax = fmaxf(X[0], fmaxf(X[1], X[2]));
    float ymin = fminf(Y[0], fminf(Y[1], Y[2]));
    float ymax = fmaxf(Y[0], fmaxf(Y[1], Y[2]));
    g_bbox[(long)b * MAXF + p] = make_float4(xmin, xmax, ymin, ymax);
}

// Conservative interval of affine w over the tile pixel-center rectangle:
// wc at tile center, radius = |ex|*hy + |ey|*hx, padded for fp slop.
__device__ __forceinline__ void edge_range(float ex, float ey, float ax, float ay,
                                           float cx, float cy, float hx, float hy,
                                           float& wmin, float& wmax) {
    float wc = ex * (cy - ay) - ey * (cx - ax);
    float r  = fabsf(ex) * hy + fabsf(ey) * hx;
    float pad = 1e-5f * (fabsf(wc) + r) + 1e-5f;
    wmin = wc - r - pad;
    wmax = wc + r + pad;
}

// 16x16 pixel tile, 128 threads, 2 pixels/thread. Each tile's triangle list
// is split across SLICES blocks (blockIdx.z = b * SLICES + s); partial z-mins
// merge via atomicMin on uint-encoded positive floats (order-independent).
__global__ __launch_bounds__(NTHREADS)
void dr_raster_kernel(int W, int H) {
    __shared__ float4 sdata[TCHUNK * 4];
    __shared__ int scount;

    int bz = blockIdx.z;
    int b = bz / SLICES;
    int s = bz - b * SLICES;
    int tile_x0 = blockIdx.x * TILE_W;
    int tile_y0 = blockIdx.y * TILE_H;
    int tid = threadIdx.x;
    int tx = tid & 7;        // 8 column-threads * 2 px
    int ty = tid >> 3;       // 16 rows

    int row = tile_y0 + ty;
    int col0 = tile_x0 + tx * 2;
    float py  = (float)row + 0.5f;
    float px0 = (float)col0 + 0.5f;

    float zmin0 = BIGF, zmin1 = BIGF;

    int cnt = g_cnt[b];
    int begin = (cnt * s) / SLICES;
    int end   = (cnt * (s + 1)) / SLICES;

    float tminx = (float)tile_x0 + 0.5f;
    float tmaxx = (float)(tile_x0 + TILE_W - 1) + 0.5f;
    float tminy = (float)tile_y0 + 0.5f;
    float tmaxy = (float)(tile_y0 + TILE_H - 1) + 0.5f;
    float tcx = 0.5f * (tminx + tmaxx);
    float tcy = 0.5f * (tminy + tmaxy);
    float thx = 0.5f * (tmaxx - tminx);
    float thy = 0.5f * (tmaxy - tminy);

    const float4* tri = &g_tri[(long)b * MAXF * 4];
    const float4* bbx = &g_bbox[(long)b * MAXF];

    for (int base = begin; base < end; base += TCHUNK) {
        if (tid == 0) scount = 0;
        __syncthreads();
        int n = min(TCHUNK, end - base);
        for (int i = tid; i < n; i += NTHREADS) {
            float4 bb = bbx[base + i];
            // bbox pre-filter
            if (bb.y >= tminx && bb.x <= tmaxx && bb.w >= tminy && bb.z <= tmaxy) {
                const float4* sp = &tri[(long)(base + i) * 4];
                float4 e0 = sp[0], e1 = sp[1], e2 = sp[2];
                float mn0, mx0, mn1, mx1, mn2, mx2;
                edge_range(e0.x, e0.y, e0.z, e0.w, tcx, tcy, thx, thy, mn0, mx0);
                edge_range(e1.x, e1.y, e1.z, e1.w, tcx, tcy, thx, thy, mn1, mx1);
                edge_range(e2.x, e2.y, e2.z, e2.w, tcx, tcy, thx, thy, mn2, mx2);
                bool pos_ok = (mx0 >= 0.f) && (mx1 >= 0.f) && (mx2 >= 0.f);
                bool neg_ok = (mn0 <= 0.f) && (mn1 <= 0.f) && (mn2 <= 0.f);
                if (pos_ok || neg_ok) {
                    int p = atomicAdd(&scount, 1);
                    sdata[p * 4 + 0] = e0;
                    sdata[p * 4 + 1] = e1;
                    sdata[p * 4 + 2] = e2;
                    sdata[p * 4 + 3] = sp[3];
                }
            }
        }
        __syncthreads();
        int m = scount;

        for (int j = 0; j < m; j++) {
            float4 d0 = sdata[j * 4 + 0];
            float4 d1 = sdata[j * 4 + 1];
            float4 d2 = sdata[j * 4 + 2];
            float4 d3 = sdata[j * 4 + 3];
            // row-shared terms (reference rounding preserved)
            float a0 = __fmul_rn(d0.x, __fsub_rn(py, d0.w));
            float a1 = __fmul_rn(d1.x, __fsub_rn(py, d1.w));
            float a2 = __fmul_rn(d2.x, __fsub_rn(py, d2.w));
#pragma unroll
            for (int k = 0; k < 2; k++) {
                float px = px0 + (float)k;
                float w0 = __fsub_rn(a0, __fmul_rn(d0.y, __fsub_rn(px, d0.z)));
                float w1 = __fsub_rn(a1, __fmul_rn(d1.y, __fsub_rn(px, d1.z)));
                float w2 = __fsub_rn(a2, __fmul_rn(d2.y, __fsub_rn(px, d2.z)));
                bool inside = (w0 >= 0.f && w1 >= 0.f && w2 >= 0.f) ||
                              (w0 <= 0.f && w1 <= 0.f && w2 <= 0.f);
                float zi = __fmaf_rn(w0, d3.x, __fmaf_rn(w1, d3.y, __fmul_rn(w2, d3.z)));
                if (inside && zi > EPSF) {
                    if (k == 0) zmin0 = fminf(zmin0, zi);
                    else        zmin1 = fminf(zmin1, zi);
                }
            }
        }
        __syncthreads();
    }

    if (row < H) {
        long off = ((long)b * H + row) * W + col0;
        // positive floats order identically as uints -> atomicMin merge
        if (zmin0 < BIGF) atomicMin(&g_zbuf[off + 0], __float_as_uint(zmin0));
        if (col0 + 1 < W && zmin1 < BIGF) atomicMin(&g_zbuf[off + 1], __float_as_uint(zmin1));
    }
}

__global__ void dr_resolve_kernel(float* __restrict__ out, int npix) {
    int i = blockIdx.x * blockDim.x + threadIdx.x;
    if (i < npix) {
        float z = __uint_as_float(g_zbuf[i]);
        out[i] = (z < 0.5f * BIGF) ? z : -1.f;
    }
}

extern "C" void kernel_launch(void* const* d_in, const int* in_sizes, int n_in,
                              void* d_out, int out_size) {
    const float* mesh    = (const float*)d_in[0];
    const float* Rm      = (const float*)d_in[1];
    const float* tv      = (const float*)d_in[2];
    const float* focal   = (const float*)d_in[3];
    const float* princpt = (const float*)d_in[4];
    const int*   face    = (const int*)  d_in[5];
    float* out = (float*)d_out;

    int B = in_sizes[1] / 9;            // R is (B,3,3)
    int V = in_sizes[0] / (3 * B);      // mesh is (B,V,3)
    int F = in_sizes[5] / 3;            // face is (F,3)
    int HW = out_size / B;              // out is (B,1,H,W)
    int W = (int)(sqrt((double)HW) + 0.5);
    int H = HW / W;
    int npix = B * H * W;

    dr_init_kernel<<<256, 256>>>(npix);
    int nset = B * F;
    dr_setup_kernel<<<(nset + 255) / 256, 256>>>(mesh, Rm, tv, focal, princpt, face, B, V, F);
    dim3 grid((W + TILE_W - 1) / TILE_W, (H + TILE_H - 1) / TILE_H, B * SLICES);
    dr_raster_kernel<<<grid, NTHREADS>>>(W, H);
    dr_resolve_kernel<<<(npix + 255) / 256, 256>>>(out, npix);
}